// round 3
// baseline (speedup 1.0000x reference)
#include <cuda_runtime.h>

// out[b, p*64+m] = x[b,m]*(w[p,0]-w[p,1]) + S[b]*w[p,1],  S[b]=sum_n x[b,n]
//
// One warp per row b. Lane j:
//   - loads float4 xv = xrow4[j & 15]            (lanes 16..31 broadcast-dup)
//   - warp-reduces S over lanes 0..15
//   - for k=0..3: writes float4 at out_row4[j + 32k]
//     element i = 4j + 128k  ->  m = (4j)&63 (matches xv),  p = 2k + (j>>4)
__global__ void __launch_bounds__(256, 8)
perm_closed_kernel(const float4* __restrict__ x4,
                   const float* __restrict__ w,
                   float4* __restrict__ out4,
                   int nrows)
{
    int warp = (int)((blockIdx.x * (unsigned)blockDim.x + threadIdx.x) >> 5);
    int lane = threadIdx.x & 31;
    if (warp >= nrows) return;

    const float4* __restrict__ xr = x4 + (size_t)warp * 16;   // 64 floats = 16 float4
    float4 xv = __ldg(&xr[lane & 15]);

    // Row sum over 64 elements: lanes 0..15 contribute, butterfly reduce.
    float part = (lane < 16) ? (xv.x + xv.y + xv.z + xv.w) : 0.0f;
    #pragma unroll
    for (int off = 16; off > 0; off >>= 1)
        part += __shfl_xor_sync(0xffffffffu, part, off);
    float S = part;

    int hi = lane >> 4;                 // 0 or 1
    float4* __restrict__ orow = out4 + (size_t)warp * 128;    // 512 floats

    #pragma unroll
    for (int k = 0; k < 4; k++) {
        int p = 2 * k + hi;
        float w0 = __ldg(&w[2 * p]);
        float w1 = __ldg(&w[2 * p + 1]);
        float wa = w0 - w1;
        float sc = S * w1;
        float4 r;
        r.x = fmaf(xv.x, wa, sc);
        r.y = fmaf(xv.y, wa, sc);
        r.z = fmaf(xv.z, wa, sc);
        r.w = fmaf(xv.w, wa, sc);
        orow[lane + 32 * k] = r;
    }
}

extern "C" void kernel_launch(void* const* d_in, const int* in_sizes, int n_in,
                              void* d_out, int out_size)
{
    const float* x = (const float*)d_in[0];   // (B, 64) fp32
    const float* w = (const float*)d_in[1];   // (8, 2) fp32
    // d_in[2] = indices (unused: closed-form 1-eye structure)

    int nrows = in_sizes[0] / 64;             // B
    int warps_per_block = 8;                  // 256 threads
    int blocks = (nrows + warps_per_block - 1) / warps_per_block;

    perm_closed_kernel<<<blocks, 256>>>(
        (const float4*)x, w, (float4*)d_out, nrows);
}